// round 9
// baseline (speedup 1.0000x reference)
#include <cuda_runtime.h>
#include <cstdint>

#define BH   32
#define LTOT 4096
#define DD   128
#define MM   640
#define TM   64
#define NMT  (MM/TM)    // 10
#define TLK  128        // k1 l-chunk
#define NCH  (LTOT/TLK) // 32
#define NSPL 4
#define CHK  (NCH/NSPL) // 8
#define TL2  128
#define NLT2 (LTOT/TL2) // 32
#define LDK  140        // plain tiles stride (k1+k2): 140 mod 32 == 12
#define PTP  136        // phiT perm stride (k1): 136 mod 32 == 8
#define LDX2 140
#define PT2  68

#define N4CTX (BH*MM*DD/4)  // 655360
#define N4KS  (BH*MM/4)     // 5120

#define INV_SSD  0.2973017787506803f
#define INV2SQD  0.04419417382415922f
#define CADD    -3.2306341575510305f

__device__ float g_ctx[(size_t)BH * MM * DD];
__device__ float g_ksum[BH * MM];
__device__ float g_ctx_part[NSPL][(size_t)BH * MM * DD];   // 42 MB
__device__ float g_ksum_part[NSPL][BH * MM];

__device__ __forceinline__ float to_tf32(float x) {
    uint32_t u;
    asm("cvt.rna.tf32.f32 %0, %1;" : "=r"(u) : "f"(x));
    return __uint_as_float(u);
}

__device__ __forceinline__ int pcol(int k) {
    return (k & ~7) | ((k & 3) << 1) | ((k >> 2) & 1);
}

__device__ __forceinline__ void mma8(float* c, const uint32_t* a, const uint32_t* b) {
    asm volatile(
        "mma.sync.aligned.m16n8k8.row.col.f32.tf32.tf32.f32 "
        "{%0,%1,%2,%3},{%4,%5,%6,%7},{%8,%9},{%0,%1,%2,%3};\n"
        : "+f"(c[0]), "+f"(c[1]), "+f"(c[2]), "+f"(c[3])
        : "r"(a[0]), "r"(a[1]), "r"(a[2]), "r"(a[3]), "r"(b[0]), "r"(b[1]));
}

__device__ __forceinline__ void lda64(uint32_t* a, const float* A0, int rstride) {
    float2 x0 = *(const float2*)A0;
    float2 x1 = *(const float2*)(A0 + 8*rstride);
    a[0] = __float_as_uint(x0.x); a[1] = __float_as_uint(x1.x);
    a[2] = __float_as_uint(x0.y); a[3] = __float_as_uint(x1.y);
}

__device__ __forceinline__ void lda32(uint32_t* a, const float* A0, int rstride) {
    a[0] = __float_as_uint(A0[0]);
    a[1] = __float_as_uint(A0[8*rstride]);
    a[2] = __float_as_uint(A0[4]);
    a[3] = __float_as_uint(A0[8*rstride + 4]);
}

// cp.async a ROWSx128 fp32 row-major tile into smem (stride LDK)
template<int ROWS>
__device__ __forceinline__ void cp_tile(uint32_t sbase, const float* g, int t) {
    #pragma unroll
    for (int r = 0; r < ROWS*32/256; r++) {
        int i = t + r*256;
        uint32_t saddr = sbase + (((i >> 5)*LDK + (i & 31)*4) << 2);
        asm volatile("cp.async.cg.shared.global [%0], [%1], 16;"
                     :: "r"(saddr), "l"(g + 4*i));
    }
}

// ---------------------------------------------------------------------------
// K1: per (bh, m-tile, l-split): ctx[64m,128d] partial over 8 chunks of 128 l
// ---------------------------------------------------------------------------
__global__ __launch_bounds__(256, 1) void k1_ctx_kernel(
    const float* __restrict__ kin, const float* __restrict__ vin,
    const float* __restrict__ proj)
{
    extern __shared__ float sm[];
    float* k_s  = sm;                 // [128][140] K chunk (cp.async -> RNA in g-pass)
    float* v_s  = k_s + TLK*LDK;      // [128][140] V chunk (cp.async) + ones col 128
    float* p_s  = v_s + TLK*LDK;      // [64][140]  P tile (cp.async, persistent)
    float* phiT = p_s + TM*LDK;       // [64 m][136] phi^T, l permuted
    float* g_s  = phiT + TM*PTP;      // [128]
    float* part = g_s + TLK;          // [256]

    const int bx = blockIdx.x;
    const int bh = bx / (NMT*NSPL);
    const int rr = bx % (NMT*NSPL);
    const int mt = rr / NSPL;
    const int ls = rr % NSPL;
    const int t  = threadIdx.x;
    const int w  = t >> 5, lane = t & 31;
    const int gid = lane >> 2, t4 = lane & 3;

    const uint32_t ks_u = (uint32_t)__cvta_generic_to_shared(k_s);
    const uint32_t vs_u = (uint32_t)__cvta_generic_to_shared(v_s);
    const uint32_t ps_u = (uint32_t)__cvta_generic_to_shared(p_s);

    const float* kg = kin + (size_t)bh*LTOT*DD;
    const float* vg = vin + (size_t)bh*LTOT*DD;
    const int c0 = ls*CHK, cend = c0 + CHK;

    // prologue: group A = {P, K[c0]}, group B = {V[c0]}
    cp_tile<TM>(ps_u, proj + (size_t)(mt*TM)*DD, t);
    cp_tile<TLK>(ks_u, kg + (size_t)c0*TLK*DD, t);
    asm volatile("cp.async.commit_group;");
    cp_tile<TLK>(vs_u, vg + (size_t)c0*TLK*DD, t);
    asm volatile("cp.async.commit_group;");

    if (t < TLK) {   // ones column for ksum-via-MMA (cols 128..135)
        *(float4*)&v_s[t*LDK + 128] = make_float4(1.f, 0.f, 0.f, 0.f);
        *(float4*)&v_s[t*LDK + 132] = make_float4(0.f, 0.f, 0.f, 0.f);
    }

    asm volatile("cp.async.wait_group 1;");   // P + K[c0] landed
    __syncthreads();

    // g-pass for K[c0]: fp32 row norms + in-place RNA rounding
    {
        int row = t & 127, half = t >> 7;
        float* kr = k_s + row*LDK + half*64;
        float s = 0.f;
        #pragma unroll
        for (int j = 0; j < 16; j++) {
            float4 x = *(float4*)(kr + j*4);
            s += x.x*x.x + x.y*x.y + x.z*x.z + x.w*x.w;
            x.x = to_tf32(x.x); x.y = to_tf32(x.y); x.z = to_tf32(x.z); x.w = to_tf32(x.w);
            *(float4*)(kr + j*4) = x;
        }
        part[t] = s;
        __syncthreads();
        if (t < TLK) g_s[t] = (part[t] + part[t + 128]) * INV2SQD;
        __syncthreads();
    }

    const int la = w & 3, mh2 = w >> 2;   // GEMM A: warp 32l x 32m
    const int mb2 = w & 1, db4 = w >> 1;  // GEMM B: warp 32m x 32d

    float ctxacc[2][4][4];
    #pragma unroll
    for (int ia = 0; ia < 2; ia++)
        #pragma unroll
        for (int nb = 0; nb < 4; nb++)
            #pragma unroll
            for (int i = 0; i < 4; i++) ctxacc[ia][nb][i] = 0.f;
    float ksacc[2][4];
    #pragma unroll
    for (int ia = 0; ia < 2; ia++)
        #pragma unroll
        for (int i = 0; i < 4; i++) ksacc[ia][i] = 0.f;

    for (int lc = c0; lc < cend; lc++) {
        const bool more = (lc + 1 < cend);

        // GEMM A: S[128l x 64m] = K_chunk @ P^T
        float c[2][4][4];
        #pragma unroll
        for (int ia = 0; ia < 2; ia++)
            #pragma unroll
            for (int nb = 0; nb < 4; nb++)
                #pragma unroll
                for (int i = 0; i < 4; i++) c[ia][nb][i] = 0.f;
        #pragma unroll
        for (int kk = 0; kk < DD; kk += 8) {
            uint32_t a[2][4], b[2];
            #pragma unroll
            for (int ia = 0; ia < 2; ia++)
                lda32(a[ia], k_s + (la*32 + ia*16 + gid)*LDK + kk + t4, LDK);
            #pragma unroll
            for (int nb = 0; nb < 4; nb++) {
                const float* B0 = p_s + (mh2*32 + nb*8 + gid)*LDK + kk + t4;
                b[0] = __float_as_uint(B0[0]);
                b[1] = __float_as_uint(B0[4]);
                mma8(c[0][nb], a[0], b);
                mma8(c[1][nb], a[1], b);
            }
        }
        __syncthreads();   // k_s reads done

        // prefetch K[lc+1] into k_s (overlaps exp + GEMM B)
        if (more) {
            cp_tile<TLK>(ks_u, kg + (size_t)(lc+1)*TLK*DD, t);
            asm volatile("cp.async.commit_group;");
        }

        // exp -> phiT[m][pcol(l)]
        #pragma unroll
        for (int ia = 0; ia < 2; ia++)
            #pragma unroll
            for (int nb = 0; nb < 4; nb++) {
                int m0 = mh2*32 + nb*8 + 2*t4;
                #pragma unroll
                for (int i = 0; i < 4; i++) {
                    int l = la*32 + ia*16 + gid + ((i >> 1) << 3);
                    float ph = __expf(fmaf(c[ia][nb][i], INV_SSD, CADD - g_s[l]));
                    phiT[(m0 + (i & 1))*PTP + pcol(l)] = to_tf32(ph);
                }
            }

        if (more) asm volatile("cp.async.wait_group 1;");   // V[lc] landed
        else      asm volatile("cp.async.wait_group 0;");
        __syncthreads();   // phiT + v_s published

        // GEMM B: ctx += phiT(32m x 128l) @ V(128l x 32d); db4==3 adds ones col
        #pragma unroll
        for (int kk = 0; kk < TLK; kk += 8) {
            uint32_t a[2][4];
            #pragma unroll
            for (int ia = 0; ia < 2; ia++)
                lda64(a[ia], phiT + (mb2*32 + ia*16 + gid)*PTP + kk + 2*t4, PTP);
            #pragma unroll
            for (int nb = 0; nb < 4; nb++) {
                uint32_t b[2];
                const float* B0 = v_s + (kk + t4)*LDK + db4*32 + nb*8 + gid;
                b[0] = __float_as_uint(B0[0]);
                b[1] = __float_as_uint(B0[4*LDK]);
                mma8(ctxacc[0][nb], a[0], b);
                mma8(ctxacc[1][nb], a[1], b);
            }
            if (db4 == 3) {
                uint32_t b[2];
                const float* B0 = v_s + (kk + t4)*LDK + 128 + gid;
                b[0] = __float_as_uint(B0[0]);
                b[1] = __float_as_uint(B0[4*LDK]);
                mma8(ksacc[0], a[0], b);
                mma8(ksacc[1], a[1], b);
            }
        }
        __syncthreads();   // v_s reads done

        if (more) {
            cp_tile<TLK>(vs_u, vg + (size_t)(lc+1)*TLK*DD, t);   // overlaps next GEMM A
            asm volatile("cp.async.commit_group;");
            asm volatile("cp.async.wait_group 1;");              // K[lc+1] landed
            __syncthreads();
            // g-pass for K[lc+1] + RNA in place
            int row = t & 127, half = t >> 7;
            float* kr = k_s + row*LDK + half*64;
            float s = 0.f;
            #pragma unroll
            for (int j = 0; j < 16; j++) {
                float4 x = *(float4*)(kr + j*4);
                s += x.x*x.x + x.y*x.y + x.z*x.z + x.w*x.w;
                x.x = to_tf32(x.x); x.y = to_tf32(x.y); x.z = to_tf32(x.z); x.w = to_tf32(x.w);
                *(float4*)(kr + j*4) = x;
            }
            part[t] = s;
            __syncthreads();
            if (t < TLK) g_s[t] = (part[t] + part[t + 128]) * INV2SQD;
            __syncthreads();
        }
    }

    float* cg = g_ctx_part[ls] + ((size_t)bh*MM + mt*TM)*DD;
    #pragma unroll
    for (int ia = 0; ia < 2; ia++)
        #pragma unroll
        for (int nb = 0; nb < 4; nb++) {
            int m0 = mb2*32 + ia*16 + gid;
            int d  = db4*32 + nb*8 + 2*t4;
            *(float2*)&cg[m0*DD + d]       = make_float2(ctxacc[ia][nb][0], ctxacc[ia][nb][1]);
            *(float2*)&cg[(m0 + 8)*DD + d] = make_float2(ctxacc[ia][nb][2], ctxacc[ia][nb][3]);
        }
    if (db4 == 3 && t4 == 0) {
        #pragma unroll
        for (int ia = 0; ia < 2; ia++) {
            int m = mb2*32 + ia*16 + gid;
            g_ksum_part[ls][bh*MM + mt*TM + m]     = ksacc[ia][0];
            g_ksum_part[ls][bh*MM + mt*TM + m + 8] = ksacc[ia][2];
        }
    }
}

// ---------------------------------------------------------------------------
// KRED: g_ctx = sum of partials; g_ksum likewise
// ---------------------------------------------------------------------------
__global__ __launch_bounds__(256) void kred_kernel()
{
    int i = blockIdx.x*256 + threadIdx.x;
    if (i < N4CTX) {
        float4 s = ((const float4*)g_ctx_part[0])[i];
        #pragma unroll
        for (int p = 1; p < NSPL; p++) {
            float4 a = ((const float4*)g_ctx_part[p])[i];
            s.x += a.x; s.y += a.y; s.z += a.z; s.w += a.w;
        }
        ((float4*)g_ctx)[i] = s;
    } else {
        int j = i - N4CTX;
        float4 s = ((const float4*)g_ksum_part[0])[j];
        #pragma unroll
        for (int p = 1; p < NSPL; p++) {
            float4 a = ((const float4*)g_ksum_part[p])[j];
            s.x += a.x; s.y += a.y; s.z += a.z; s.w += a.w;
        }
        ((float4*)g_ksum)[j] = s;
    }
}

// ===================== K2 (unchanged from R7/R8) ===========================
__device__ __forceinline__ void cp_tile2(uint32_t sbase, const float* g, int t) {
    #pragma unroll
    for (int r = 0; r < 8; r++) {
        int i = t + r*256;
        uint32_t saddr = sbase + (((i >> 5)*LDX2 + (i & 31)*4) << 2);
        asm volatile("cp.async.cg.shared.global [%0], [%1], 16;"
                     :: "r"(saddr), "l"(g + 4*i));
    }
}

__global__ __launch_bounds__(256, 1) void k2_out_kernel(
    const float* __restrict__ qin, const float* __restrict__ proj,
    float* __restrict__ out)
{
    extern __shared__ float sm[];
    float* q_s   = sm;
    float* p_buf = q_s + TL2*LDX2;
    float* c_buf = p_buf + TM*LDX2;
    float* phi_s = c_buf + TM*LDX2;
    float* g_s   = phi_s + TL2*PT2;
    float* dinv  = g_s + TL2;

    const int bh = blockIdx.x / NLT2;
    const int lt = blockIdx.x % NLT2;
    const int t  = threadIdx.x;
    const int w  = t >> 5, lane = t & 31;
    const int gid = lane >> 2, t4 = lane & 3;

    const uint32_t pb_u = (uint32_t)__cvta_generic_to_shared(p_buf);
    const uint32_t cb_u = (uint32_t)__cvta_generic_to_shared(c_buf);

    cp_tile2(pb_u, proj, t);
    asm volatile("cp.async.commit_group;");

    {
        const float4* Qg = (const float4*)(qin + ((size_t)bh*LTOT + lt*TL2)*DD);
        #pragma unroll
        for (int r = 0; r < 16; r++) {
            int i = t + r*256;
            float4 v = Qg[i];
            float ss = v.x*v.x + v.y*v.y + v.z*v.z + v.w*v.w;
            ss += __shfl_xor_sync(0xffffffffu, ss, 16);
            ss += __shfl_xor_sync(0xffffffffu, ss, 8);
            ss += __shfl_xor_sync(0xffffffffu, ss, 4);
            ss += __shfl_xor_sync(0xffffffffu, ss, 2);
            ss += __shfl_xor_sync(0xffffffffu, ss, 1);
            if (lane == 0) g_s[r*8 + w] = ss * INV2SQD;
            v.x = to_tf32(v.x); v.y = to_tf32(v.y); v.z = to_tf32(v.z); v.w = to_tf32(v.w);
            *(float4*)&q_s[(i>>5)*LDX2 + (i&31)*4] = v;
        }
    }

    const int lb = w & 3;
    const int mh = w >> 2;
    const int db = w >> 2;

    float oacc[2][8][4];
    #pragma unroll
    for (int ia = 0; ia < 2; ia++)
        #pragma unroll
        for (int nb = 0; nb < 8; nb++)
            #pragma unroll
            for (int i = 0; i < 4; i++) oacc[ia][nb][i] = 0.f;
    float dks[2][4];
    #pragma unroll
    for (int ia = 0; ia < 2; ia++)
        #pragma unroll
        for (int i = 0; i < 4; i++) dks[ia][i] = 0.f;

    for (int mc = 0; mc < NMT; mc++) {
        __syncthreads();
        cp_tile2(cb_u, g_ctx + ((size_t)bh*MM + mc*TM)*DD, t);
        asm volatile("cp.async.commit_group;");
        asm volatile("cp.async.wait_group 1;");
        __syncthreads();

        float c[2][4][4];
        #pragma unroll
        for (int ia = 0; ia < 2; ia++)
            #pragma unroll
            for (int nb = 0; nb < 4; nb++)
                #pragma unroll
                for (int i = 0; i < 4; i++) c[ia][nb][i] = 0.f;
        #pragma unroll
        for (int kk = 0; kk < DD; kk += 8) {
            uint32_t a[2][4], b[2];
            #pragma unroll
            for (int ia = 0; ia < 2; ia++)
                lda32(a[ia], q_s + (lb*32 + ia*16 + gid)*LDX2 + kk + t4, LDX2);
            #pragma unroll
            for (int nb = 0; nb < 4; nb++) {
                const float* B0 = p_buf + (mh*32 + nb*8 + gid)*LDX2 + kk + t4;
                b[0] = __float_as_uint(B0[0]);
                b[1] = __float_as_uint(B0[4]);
                mma8(c[0][nb], a[0], b);
                mma8(c[1][nb], a[1], b);
            }
        }
        __syncthreads();

        if (mc + 1 < NMT) cp_tile2(pb_u, proj + (size_t)((mc+1)*TM)*DD, t);
        asm volatile("cp.async.commit_group;");

        #pragma unroll
        for (int ia = 0; ia < 2; ia++)
            #pragma unroll
            for (int nb = 0; nb < 4; nb++) {
                int m0 = mh*32 + nb*8 + 2*t4;
                #pragma unroll
                for (int i = 0; i < 4; i++) {
                    int l = lb*32 + ia*16 + gid + ((i >> 1) << 3);
                    float ph = __expf(fmaf(c[ia][nb][i], INV_SSD, CADD - g_s[l]));
                    phi_s[l*PT2 + m0 + (i & 1)] = to_tf32(ph);
                }
            }
        if (t < TM) {
            float ks = to_tf32(g_ksum[bh*MM + mc*TM + t]);
            *(float4*)&c_buf[t*LDX2 + 128] = make_float4(ks, 0.f, 0.f, 0.f);
            *(float4*)&c_buf[t*LDX2 + 132] = make_float4(0.f, 0.f, 0.f, 0.f);
        }
        asm volatile("cp.async.wait_group 1;");
        __syncthreads();

        #pragma unroll
        for (int kk = 0; kk < TM; kk += 8) {
            uint32_t a[2][4];
            #pragma unroll
            for (int ia = 0; ia < 2; ia++)
                lda32(a[ia], phi_s + (lb*32 + ia*16 + gid)*PT2 + kk + t4, PT2);
            #pragma unroll
            for (int nb = 0; nb < 8; nb++) {
                uint32_t b[2];
                const float* B0 = c_buf + (kk + t4)*LDX2 + db*64 + nb*8 + gid;
                b[0] = __float_as_uint(B0[0]);
                b[1] = __float_as_uint(B0[4*LDX2]);
                mma8(oacc[0][nb], a[0], b);
                mma8(oacc[1][nb], a[1], b);
            }
            if (db == 1) {
                uint32_t b[2];
                const float* B0 = c_buf + (kk + t4)*LDX2 + 128 + gid;
                b[0] = __float_as_uint(B0[0]);
                b[1] = __float_as_uint(B0[4*LDX2]);
                mma8(dks[0], a[0], b);
                mma8(dks[1], a[1], b);
            }
        }
    }

    if (db == 1 && t4 == 0) {
        #pragma unroll
        for (int ia = 0; ia < 2; ia++) {
            int l = lb*32 + ia*16 + gid;
            dinv[l]     = 1.0f / dks[ia][0];
            dinv[l + 8] = 1.0f / dks[ia][2];
        }
    }
    __syncthreads();

    float* og = out + ((size_t)bh*LTOT + lt*TL2)*DD;
    #pragma unroll
    for (int ia = 0; ia < 2; ia++)
        #pragma unroll
        for (int nb = 0; nb < 8; nb++) {
            int l0 = lb*32 + ia*16 + gid;
            int d  = db*64 + nb*8 + 2*t4;
            float i0 = dinv[l0], i1 = dinv[l0 + 8];
            *(float2*)&og[l0*DD + d]       = make_float2(oacc[ia][nb][0]*i0, oacc[ia][nb][1]*i0);
            *(float2*)&og[(l0 + 8)*DD + d] = make_float2(oacc[ia][nb][2]*i1, oacc[ia][nb][3]*i1);
        }
}

extern "C" void kernel_launch(void* const* d_in, const int* in_sizes, int n_in,
                              void* d_out, int out_size) {
    const float* q    = (const float*)d_in[0];
    const float* k    = (const float*)d_in[1];
    const float* v    = (const float*)d_in[2];
    const float* proj = (const float*)d_in[3];
    float* out = (float*)d_out;

    size_t smem1 = (2*TLK*LDK + TM*LDK + TM*PTP + TLK + 256) * sizeof(float);    // ~210.5 KB
    size_t smem2 = (TL2*LDX2 + 2*TM*LDX2 + TL2*PT2 + TL2 + TL2) * sizeof(float); // ~179 KB
    cudaFuncSetAttribute(k1_ctx_kernel, cudaFuncAttributeMaxDynamicSharedMemorySize, (int)smem1);
    cudaFuncSetAttribute(k2_out_kernel, cudaFuncAttributeMaxDynamicSharedMemorySize, (int)smem2);

    k1_ctx_kernel<<<BH * NMT * NSPL, 256, smem1>>>(k, v, proj);
    kred_kernel<<<(N4CTX + N4KS) / 256, 256>>>();
    k2_out_kernel<<<BH * NLT2, 256, smem2>>>(q, proj, out);
}